// round 2
// baseline (speedup 1.0000x reference)
#include <cuda_runtime.h>
#include <cmath>

#define S_LEN  1024
#define BATCHN 128
#define IDIM   256
#define HDIM   512
#define ODIM   64

typedef unsigned long long ull;

// ---------- f32x2 packed-FMA helpers (FFMA2: 2x fp32 FMA rate on sm_103a) ----------
__device__ __forceinline__ ull pk2(float x, float y) {
    ull r; asm("mov.b64 %0, {%1, %2};" : "=l"(r) : "f"(x), "f"(y)); return r;
}
__device__ __forceinline__ ull splat2(float x) {
    ull r; asm("mov.b64 %0, {%1, %1};" : "=l"(r) : "f"(x)); return r;
}
__device__ __forceinline__ ull ffma2(ull a, ull b, ull c) {
    ull d; asm("fma.rn.f32x2 %0, %1, %2, %3;" : "=l"(d) : "l"(a), "l"(b), "l"(c)); return d;
}
__device__ __forceinline__ float2 upk2(ull v) {
    float2 f; asm("mov.b64 {%0, %1}, %2;" : "=f"(f.x), "=f"(f.y) : "l"(v)); return f;
}
__device__ __forceinline__ unsigned s2u32(const void* p) {
    unsigned a;
    asm("{ .reg .u64 t; cvta.to.shared.u64 t, %1; cvt.u32.u64 %0, t; }" : "=r"(a) : "l"(p));
    return a;
}
__device__ __forceinline__ unsigned mapa_rank(unsigned a, unsigned r) {
    unsigned d; asm("mapa.shared::cluster.u32 %0, %1, %2;" : "=r"(d) : "r"(a), "r"(r));
    return d;
}

// ---------- scratch (device globals: allocation-free rule) ----------
__device__ float g_xp[(size_t)BATCHN * S_LEN * HDIM];  // X@W_ih + b_hh, layout [b][s][h]
__device__ float g_h [(size_t)BATCHN * S_LEN * HDIM];  // all hidden states, [b][s][h]

// ============================================================================
// Kernel A: g_xp[M,512] = X[M,256] @ W_ih[256,512] + b_hh, M = 131072
// BM=128 BN=128 BK=16, 256 threads, 8m x 8n per thread, f32x2 accumulators.
// ============================================================================
__global__ void __launch_bounds__(256, 2) xproj_kernel(
    const float* __restrict__ X, const float* __restrict__ Wih,
    const float* __restrict__ bhh)
{
    __shared__ float As[128][17];   // [m][k] padded
    __shared__ float Bs[16][128];   // [k][n]
    const int tid = threadIdx.x;
    const int m0 = blockIdx.x * 128;
    const int n0 = blockIdx.y * 128;
    const int tx = tid & 15, ty = tid >> 4;

    ull acc[8][4];
#pragma unroll
    for (int i = 0; i < 8; i++)
#pragma unroll
        for (int j = 0; j < 4; j++) acc[i][j] = 0ull;

    for (int k0 = 0; k0 < IDIM; k0 += 16) {
#pragma unroll
        for (int i = 0; i < 2; i++) {               // A tile: 128x16
            int f4  = tid + i * 256;
            int row = f4 >> 2;
            int c4  = (f4 & 3) << 2;
            float4 v = *(const float4*)(X + (size_t)(m0 + row) * IDIM + k0 + c4);
            As[row][c4 + 0] = v.x; As[row][c4 + 1] = v.y;
            As[row][c4 + 2] = v.z; As[row][c4 + 3] = v.w;
        }
#pragma unroll
        for (int i = 0; i < 2; i++) {               // B tile: 16x128
            int f4  = tid + i * 256;
            int row = f4 >> 5;
            int c4  = (f4 & 31) << 2;
            *(float4*)&Bs[row][c4] =
                *(const float4*)(Wih + (size_t)(k0 + row) * HDIM + n0 + c4);
        }
        __syncthreads();
#pragma unroll
        for (int k = 0; k < 16; k++) {
            ulonglong2 bv0 = *(const ulonglong2*)&Bs[k][tx * 4];
            ulonglong2 bv1 = *(const ulonglong2*)&Bs[k][64 + tx * 4];
#pragma unroll
            for (int i = 0; i < 8; i++) {
                ull a2 = splat2(As[ty * 8 + i][k]);
                acc[i][0] = ffma2(a2, bv0.x, acc[i][0]);
                acc[i][1] = ffma2(a2, bv0.y, acc[i][1]);
                acc[i][2] = ffma2(a2, bv1.x, acc[i][2]);
                acc[i][3] = ffma2(a2, bv1.y, acc[i][3]);
            }
        }
        __syncthreads();
    }

    float bias[8];
#pragma unroll
    for (int j = 0; j < 2; j++) {
        bias[j * 4 + 0] = bhh[n0 + j * 64 + tx * 4 + 0];
        bias[j * 4 + 1] = bhh[n0 + j * 64 + tx * 4 + 1];
        bias[j * 4 + 2] = bhh[n0 + j * 64 + tx * 4 + 2];
        bias[j * 4 + 3] = bhh[n0 + j * 64 + tx * 4 + 3];
    }
#pragma unroll
    for (int i = 0; i < 8; i++) {
        float* dst = g_xp + (size_t)(m0 + ty * 8 + i) * HDIM + n0;
#pragma unroll
        for (int j = 0; j < 4; j++) {
            int n = (j < 2) ? (tx * 4 + j * 2) : (64 + tx * 4 + (j - 2) * 2);
            float2 v = upk2(acc[i][j]);
            v.x += bias[(j < 2) ? (j * 2)     : (4 + (j - 2) * 2)];
            v.y += bias[(j < 2) ? (j * 2 + 1) : (5 + (j - 2) * 2)];
            *(float2*)(dst + n) = v;
        }
    }
}

// ============================================================================
// Kernel B: serial recurrence. 16 clusters x 8 CTAs. Rank r owns W_hh columns
// [64r,64r+64) in smem; cluster g owns batch rows [8g,8g+8). Per step:
//  phase1: warp w does K-chunk [64w,64w+64) partial dots (f32x2)
//  phase2: reduce + xp + tanh, push h-slice to all 8 cluster CTAs (DSMEM),
//  one cluster.sync per step, double-buffered h.
// ============================================================================
#define NT 256
// smem float offsets: Ws[512*64] | hb[2*512*8] | part[8*8*68]
#define OFF_WS   0
#define OFF_HB   32768
#define OFF_PART 40960
#define SMEMB_FLOATS (40960 + 8 * 8 * 68)
#define SMEMB_BYTES  (SMEMB_FLOATS * 4)

__global__ void __launch_bounds__(NT, 1) __cluster_dims__(8, 1, 1)
rnn_kernel(const float* __restrict__ Whh)
{
    extern __shared__ float sm[];
    float* Ws   = sm + OFF_WS;    // [k][j], j stride 1, k stride 64
    float* hb   = sm + OFF_HB;    // [buf][k][b], b stride 1 (8), k stride 8
    float* part = sm + OFF_PART;  // [w][b][j], j stride 1, b stride 68, w stride 544

    const int tid  = threadIdx.x;
    const int rank = blockIdx.x & 7;
    const int g    = blockIdx.x >> 3;
    const int c0   = rank * 64;

    // Load W_hh column slice once (HBM -> smem, 128KB)
    for (int f4 = tid; f4 < HDIM * 64 / 4; f4 += NT) {
        int k  = f4 >> 4;
        int j4 = (f4 & 15) << 2;
        *(float4*)(Ws + k * 64 + j4) =
            *(const float4*)(Whh + (size_t)k * HDIM + c0 + j4);
    }
    // h0 = 0 (both buffers)
    for (int i = tid; i < 2 * HDIM * 8; i += NT) hb[i] = 0.f;
    __syncthreads();
    asm volatile("barrier.cluster.arrive.aligned;" ::: "memory");
    asm volatile("barrier.cluster.wait.aligned;"   ::: "memory");

    const int w    = tid >> 5, lane = tid & 31;
    const int rg   = lane >> 4, cg  = lane & 15;   // phase-1 tile coords
    const int kbeg = w * 64;
    const int jj   = tid >> 2;                     // phase-2 own column (0..63)
    const int b2   = (tid & 3) << 1;               // phase-2 batch pair base

    const float* xp0 = g_xp + ((size_t)(g * 8 + b2) * S_LEN) * HDIM + c0 + jj;
    const float* xp1 = xp0 + (size_t)S_LEN * HDIM;
    float* gh0 = g_h + ((size_t)(g * 8 + b2) * S_LEN) * HDIM + c0 + jj;
    float* gh1 = gh0 + (size_t)S_LEN * HDIM;

    // precompute DSMEM target addresses (one per rank)
    unsigned hb_loc = s2u32(hb) + (unsigned)((c0 + jj) * 32 + b2 * 4);
    unsigned peer[8];
#pragma unroll
    for (int r = 0; r < 8; r++) peer[r] = mapa_rank(hb_loc, (unsigned)r);

    const float* wsrow = Ws + kbeg * 64 + cg * 4;

    for (int t = 0; t < S_LEN; t++) {
        const int cur = t & 1, nxt = cur ^ 1;
        // prefetch xp for this step (consumed after phase 1)
        float xv0 = xp0[(size_t)t * HDIM];
        float xv1 = xp1[(size_t)t * HDIM];

        // ---- phase 1: partial dot products over this warp's K chunk ----
        const float* hrow = hb + cur * 4096 + kbeg * 8 + rg * 4;
        ull acc[4][2];
#pragma unroll
        for (int q = 0; q < 4; q++) { acc[q][0] = 0ull; acc[q][1] = 0ull; }
#pragma unroll 8
        for (int k = 0; k < 64; k++) {
            float4     wv = *(const float4*)(wsrow + k * 64);
            ulonglong2 hp = *(const ulonglong2*)(hrow + k * 8);
            ull w0 = splat2(wv.x), w1 = splat2(wv.y);
            ull w2 = splat2(wv.z), w3 = splat2(wv.w);
            acc[0][0] = ffma2(w0, hp.x, acc[0][0]);
            acc[0][1] = ffma2(w0, hp.y, acc[0][1]);
            acc[1][0] = ffma2(w1, hp.x, acc[1][0]);
            acc[1][1] = ffma2(w1, hp.y, acc[1][1]);
            acc[2][0] = ffma2(w2, hp.x, acc[2][0]);
            acc[2][1] = ffma2(w2, hp.y, acc[2][1]);
            acc[3][0] = ffma2(w3, hp.x, acc[3][0]);
            acc[3][1] = ffma2(w3, hp.y, acc[3][1]);
        }
        // store partials: part[w][b][cg*4 .. +3]
        {
            float2 a00 = upk2(acc[0][0]), a10 = upk2(acc[1][0]);
            float2 a20 = upk2(acc[2][0]), a30 = upk2(acc[3][0]);
            float2 a01 = upk2(acc[0][1]), a11 = upk2(acc[1][1]);
            float2 a21 = upk2(acc[2][1]), a31 = upk2(acc[3][1]);
            float* pw = part + w * 544 + cg * 4;
            *(float4*)(pw + (rg * 4 + 0) * 68) = make_float4(a00.x, a10.x, a20.x, a30.x);
            *(float4*)(pw + (rg * 4 + 1) * 68) = make_float4(a00.y, a10.y, a20.y, a30.y);
            *(float4*)(pw + (rg * 4 + 2) * 68) = make_float4(a01.x, a11.x, a21.x, a31.x);
            *(float4*)(pw + (rg * 4 + 3) * 68) = make_float4(a01.y, a11.y, a21.y, a31.y);
        }
        __syncthreads();

        // ---- phase 2: reduce over 8 warps, + xp, tanh, scatter h ----
        float s0 = xv0, s1 = xv1;
        const float* pb = part + b2 * 68 + jj;
#pragma unroll
        for (int r = 0; r < 8; r++) {
            s0 += pb[r * 544];
            s1 += pb[r * 544 + 68];
        }
        float h0 = tanhf(s0);
        float h1 = tanhf(s1);
        gh0[(size_t)t * HDIM] = h0;
        gh1[(size_t)t * HDIM] = h1;

        unsigned boff = (unsigned)(nxt * 16384);
#pragma unroll
        for (int r = 0; r < 8; r++) {
            asm volatile("st.shared::cluster.v2.f32 [%0], {%1, %2};"
                         :: "r"(peer[r] + boff), "f"(h0), "f"(h1) : "memory");
        }
        asm volatile("barrier.cluster.arrive.aligned;" ::: "memory");
        asm volatile("barrier.cluster.wait.aligned;"   ::: "memory");
    }
}

// ============================================================================
// Kernel C: out[M,64] = g_h[M,512] @ W_ho[512,64] + b_ho, M = 131072
// BM=128 BN=64 BK=16, 256 threads, 8m x 4n per thread.
// ============================================================================
__global__ void __launch_bounds__(256) out_kernel(
    const float* __restrict__ Who, const float* __restrict__ bho,
    float* __restrict__ out)
{
    __shared__ float As[128][17];
    __shared__ float Bs[16][64];
    const int tid = threadIdx.x;
    const int m0 = blockIdx.x * 128;
    const int tx = tid & 15, ty = tid >> 4;

    ull acc[8][2];
#pragma unroll
    for (int i = 0; i < 8; i++) { acc[i][0] = 0ull; acc[i][1] = 0ull; }

    for (int k0 = 0; k0 < HDIM; k0 += 16) {
#pragma unroll
        for (int i = 0; i < 2; i++) {               // A tile: 128x16
            int f4  = tid + i * 256;
            int row = f4 >> 2;
            int c4  = (f4 & 3) << 2;
            float4 v = *(const float4*)(g_h + (size_t)(m0 + row) * HDIM + k0 + c4);
            As[row][c4 + 0] = v.x; As[row][c4 + 1] = v.y;
            As[row][c4 + 2] = v.z; As[row][c4 + 3] = v.w;
        }
        {                                           // B tile: 16x64
            int row = tid >> 4;
            int c4  = (tid & 15) << 2;
            *(float4*)&Bs[row][c4] =
                *(const float4*)(Who + (size_t)(k0 + row) * ODIM + c4);
        }
        __syncthreads();
#pragma unroll
        for (int k = 0; k < 16; k++) {
            ulonglong2 bv = *(const ulonglong2*)&Bs[k][tx * 4];
#pragma unroll
            for (int i = 0; i < 8; i++) {
                ull a2 = splat2(As[ty * 8 + i][k]);
                acc[i][0] = ffma2(a2, bv.x, acc[i][0]);
                acc[i][1] = ffma2(a2, bv.y, acc[i][1]);
            }
        }
        __syncthreads();
    }

    float bb0 = bho[tx * 4 + 0], bb1 = bho[tx * 4 + 1];
    float bb2 = bho[tx * 4 + 2], bb3 = bho[tx * 4 + 3];
#pragma unroll
    for (int i = 0; i < 8; i++) {
        float2 v0 = upk2(acc[i][0]); v0.x += bb0; v0.y += bb1;
        float2 v1 = upk2(acc[i][1]); v1.x += bb2; v1.y += bb3;
        float* dst = out + (size_t)(m0 + ty * 8 + i) * ODIM + tx * 4;
        *(float2*)(dst + 0) = v0;
        *(float2*)(dst + 2) = v1;
    }
}

// ============================================================================
extern "C" void kernel_launch(void* const* d_in, const int* in_sizes, int n_in,
                              void* d_out, int out_size)
{
    const float* X   = (const float*)d_in[0];   // [128,1024,256]
    const float* Whh = (const float*)d_in[1];   // [512,512]
    const float* Wih = (const float*)d_in[2];   // [256,512]
    const float* bhh = (const float*)d_in[3];   // [512]
    const float* Who = (const float*)d_in[4];   // [512,64]
    const float* bho = (const float*)d_in[5];   // [64]
    float* out = (float*)d_out;                 // [128,1024,64]

    cudaFuncSetAttribute(rnn_kernel,
                         cudaFuncAttributeMaxDynamicSharedMemorySize,
                         SMEMB_BYTES);

    xproj_kernel<<<dim3(1024, 4, 1), 256>>>(X, Wih, bhh);
    rnn_kernel<<<128, 256, SMEMB_BYTES>>>(Whh);
    out_kernel<<<1024, 256>>>(Who, bho, out);
}